// round 1
// baseline (speedup 1.0000x reference)
#include <cuda_runtime.h>

// ---------------- problem constants ----------------
// B=4, T=2048, C=1024, H=16, D=64; M = B*T = 8192
#define MB 8192
#define CC 1024
#define C3 3072
#define NH 16
#define HD 64
#define TT 2048
#define BH 64        // B*H

// ---------------- device scratch (no allocs allowed) ----------------
__device__ float g_qkv[(size_t)MB * C3];              // 100.7 MB
__device__ float g_q[(size_t)BH * TT * HD];           // 33.6 MB
__device__ float g_k[(size_t)BH * TT * HD];
__device__ float g_v[(size_t)BH * TT * HD];
__device__ float g_y[(size_t)MB * CC];                // 33.6 MB

// ---------------- SGEMM: 128x128 tile, K-tile 8, 256 thr, 8x8/thread ----------------
// MODE 0: C(g_qkv) = Aext(x) @ Bmat(W_attn)
// MODE 1: C(Cext=out) = g_y @ Bmat(W_proj)
template <int MODE>
__global__ __launch_bounds__(256) void sgemm_kernel(const float* __restrict__ Aext,
                                                    const float* __restrict__ Bmat,
                                                    float* __restrict__ Cext,
                                                    int M, int N, int K)
{
    const float* A = (MODE == 0) ? Aext : g_y;
    float*       C = (MODE == 0) ? g_qkv : Cext;

    __shared__ float As[8][128];
    __shared__ float Bs[8][128];

    const int tid = threadIdx.x;
    const int tx = tid & 15;        // 0..15
    const int ty = tid >> 4;        // 0..15
    const int m0 = blockIdx.y * 128;
    const int n0 = blockIdx.x * 128;

    // A-tile loader: 128 rows x 8 cols -> 256 float4 (2 per row along K)
    const int ar = tid >> 1;
    const int ac = (tid & 1) * 4;
    // B-tile loader: 8 rows x 128 cols -> 256 float4
    const int br = tid >> 5;
    const int bc = (tid & 31) * 4;

    float acc[8][8];
#pragma unroll
    for (int i = 0; i < 8; i++)
#pragma unroll
        for (int j = 0; j < 8; j++) acc[i][j] = 0.f;

    for (int kk = 0; kk < K; kk += 8) {
        float4 av = *(const float4*)&A[(size_t)(m0 + ar) * K + kk + ac];
        float4 bv = *(const float4*)&Bmat[(size_t)(kk + br) * N + n0 + bc];
        As[ac + 0][ar] = av.x;
        As[ac + 1][ar] = av.y;
        As[ac + 2][ar] = av.z;
        As[ac + 3][ar] = av.w;
        *(float4*)&Bs[br][bc] = bv;
        __syncthreads();

#pragma unroll
        for (int k = 0; k < 8; k++) {
            float a[8], b[8];
#pragma unroll
            for (int i = 0; i < 8; i++) a[i] = As[k][ty * 8 + i];
#pragma unroll
            for (int j = 0; j < 8; j++) b[j] = Bs[k][tx * 8 + j];
#pragma unroll
            for (int i = 0; i < 8; i++)
#pragma unroll
                for (int j = 0; j < 8; j++) acc[i][j] += a[i] * b[j];
        }
        __syncthreads();
    }

#pragma unroll
    for (int i = 0; i < 8; i++) {
        float* crow = &C[(size_t)(m0 + ty * 8 + i) * N + n0 + tx * 8];
        *(float4*)crow       = make_float4(acc[i][0], acc[i][1], acc[i][2], acc[i][3]);
        *(float4*)(crow + 4) = make_float4(acc[i][4], acc[i][5], acc[i][6], acc[i][7]);
    }
}

// ---------------- RoPE + split/transpose to (BH, T, D) ----------------
__global__ __launch_bounds__(256) void rope_kernel()
{
    int idx = blockIdx.x * blockDim.x + threadIdx.x;  // over B*T*H*D = 8388608
    if (idx >= 4 * 2048 * 16 * 64) return;
    const int d = idx & 63;
    const int h = (idx >> 6) & 15;
    const int t = (idx >> 10) & 2047;
    const int b = idx >> 21;

    const size_t row  = (size_t)(b * TT + t);
    const size_t base = row * C3 + h * HD;

    const float qv = g_qkv[base + d];
    const float kv = g_qkv[base + 1024 + d];
    const float vv = g_qkv[base + 2048 + d];
    const int   dro = (d < 32) ? d + 32 : d - 32;
    const float qo = g_qkv[base + dro];
    const float ko = g_qkv[base + 1024 + dro];
    const float sgn = (d < 32) ? -1.f : 1.f;

    const int j = d & 31;
    // inv_freq = 10000^(-(2j)/64) = 2^(-(2j)/64 * log2(10000))
    const float inv = exp2f(-(float)(2 * j) * (13.287712379549449f / 64.f));
    const float ang = (float)t * inv;
    float sn, cs;
    sincosf(ang, &sn, &cs);

    const size_t o = ((size_t)(b * NH + h) * TT + t) * HD + d;
    g_q[o] = qv * cs + sgn * qo * sn;
    g_k[o] = kv * cs + sgn * ko * sn;
    g_v[o] = vv;
}

// ---------------- flash attention, fp32, row-per-thread ----------------
// block = 128 threads = 128 query rows; grid = (T/128, B*H)
__global__ __launch_bounds__(128) void attn_kernel()
{
    __shared__ float Ks[32 * 64];     // 8 KB
    __shared__ float Vs[32 * 64];     // 8 KB
    __shared__ float Ssh[32][128];    // 16 KB (per-thread private score staging)

    const int bh  = blockIdx.y;
    const int tid = threadIdx.x;
    const int qt  = blockIdx.x * 128 + tid;

    const float* Qp = g_q + ((size_t)bh * TT + qt) * HD;
    const float* Kb = g_k + (size_t)bh * TT * HD;
    const float* Vb = g_v + (size_t)bh * TT * HD;

    float q[64], o[64];
#pragma unroll
    for (int d = 0; d < 64; d++) { q[d] = Qp[d]; o[d] = 0.f; }
    float m = -1e30f, l = 0.f;
    const float scale = 0.125f;  // 1/sqrt(64)

    for (int kt = 0; kt < TT / 32; kt++) {
        const float4* ksrc = (const float4*)(Kb + (size_t)kt * 32 * 64);
        const float4* vsrc = (const float4*)(Vb + (size_t)kt * 32 * 64);
        float4* kdst = (float4*)Ks;
        float4* vdst = (float4*)Vs;
#pragma unroll
        for (int i = 0; i < 4; i++) {
            kdst[i * 128 + tid] = ksrc[i * 128 + tid];
            vdst[i * 128 + tid] = vsrc[i * 128 + tid];
        }
        __syncthreads();

        // pass 1: scores + running max
        float mx = m;
        for (int jj = 0; jj < 32; jj++) {
            const float* kr = &Ks[jj * 64];
            float acc = 0.f;
#pragma unroll
            for (int d = 0; d < 64; d++) acc += q[d] * kr[d];
            acc *= scale;
            Ssh[jj][tid] = acc;
            mx = fmaxf(mx, acc);
        }

        // rescale previous accumulation
        const float corr = expf(m - mx);
        l *= corr;
#pragma unroll
        for (int d = 0; d < 64; d++) o[d] *= corr;

        // pass 2: exp + PV accumulate
        for (int jj = 0; jj < 32; jj++) {
            const float p = expf(Ssh[jj][tid] - mx);
            l += p;
            const float* vr = &Vs[jj * 64];
#pragma unroll
            for (int d = 0; d < 64; d++) o[d] += p * vr[d];
        }
        m = mx;
        __syncthreads();
    }

    const int b = bh >> 4, h = bh & 15;
    const float inv_l = 1.f / l;
    float* yp = g_y + ((size_t)b * TT + qt) * CC + h * HD;
#pragma unroll
    for (int d = 0; d < 64; d++) yp[d] = o[d] * inv_l;
}

// ---------------- launch ----------------
extern "C" void kernel_launch(void* const* d_in, const int* in_sizes, int n_in,
                              void* d_out, int out_size)
{
    const float* x      = (const float*)d_in[0];  // (4,2048,1024)
    const float* W_attn = (const float*)d_in[1];  // (1024,3072)
    const float* W_proj = (const float*)d_in[2];  // (1024,1024)
    float* out = (float*)d_out;                   // (4,2048,1024)

    // 1) qkv = x @ W_attn
    sgemm_kernel<0><<<dim3(C3 / 128, MB / 128), 256>>>(x, W_attn, nullptr, MB, C3, CC);
    // 2) RoPE + split to (BH,T,D)
    rope_kernel<<<(4 * 2048 * 16 * 64 + 255) / 256, 256>>>();
    // 3) attention -> g_y (B,T,C layout)
    attn_kernel<<<dim3(TT / 128, BH), 128>>>();
    // 4) out = g_y @ W_proj
    sgemm_kernel<1><<<dim3(CC / 128, MB / 128), 256>>>(nullptr, W_proj, out, MB, CC, CC);
}

// round 2
// speedup vs baseline: 2.0969x; 2.0969x over previous
#include <cuda_runtime.h>
#include <cuda_bf16.h>
#include <cstdint>

typedef __nv_bfloat16 bf16;

#define MB 8192       // B*T
#define TT 2048
#define BH 64         // B*H

// ---------------- device scratch ----------------
__device__ bf16  g_xe [(size_t)MB * 2048];        // x split   [hi(1024) | lo(1024)] row-major
__device__ bf16  g_wat[(size_t)3072 * 2048];      // W_attn^T split, n-major
__device__ bf16  g_wpt[(size_t)1024 * 2048];      // W_proj^T split, n-major
__device__ float g_qkv[(size_t)MB * 3072];        // qkv fp32
__device__ bf16  g_qe [(size_t)BH * TT * 128];    // Q rope split [hi(64)|lo(64)]
__device__ bf16  g_ke [(size_t)BH * TT * 128];    // K rope split
__device__ bf16  g_vt [(size_t)BH * 64 * 2 * TT]; // V dim-major [hi(T)|lo(T)] per dim
__device__ bf16  g_ye [(size_t)MB * 2048];        // attention out split

// ---------------- helpers ----------------
__device__ __forceinline__ void cpa16(void* s, const void* g) {
    uint32_t sa = (uint32_t)__cvta_generic_to_shared(s);
    asm volatile("cp.async.ca.shared.global [%0], [%1], 16;\n" :: "r"(sa), "l"(g));
}
__device__ __forceinline__ void cp_commit() { asm volatile("cp.async.commit_group;\n"); }
__device__ __forceinline__ void cp_wait0()  { asm volatile("cp.async.wait_group 0;\n"); }

__device__ __forceinline__ void mma16816(float* c, const uint32_t* a, const uint32_t* b) {
    asm volatile("mma.sync.aligned.m16n8k16.row.col.f32.bf16.bf16.f32 "
        "{%0,%1,%2,%3}, {%4,%5,%6,%7}, {%8,%9}, {%0,%1,%2,%3};"
        : "+f"(c[0]), "+f"(c[1]), "+f"(c[2]), "+f"(c[3])
        : "r"(a[0]), "r"(a[1]), "r"(a[2]), "r"(a[3]), "r"(b[0]), "r"(b[1]));
}

// split pair (a,b) -> packed hi bf16x2 (return) and lo bf16x2 (out param)
__device__ __forceinline__ uint32_t pack_hi_lo(float a, float b, uint32_t& lo) {
    bf16 ha = __float2bfloat16(a), hb = __float2bfloat16(b);
    bf16 la = __float2bfloat16(a - __bfloat162float(ha));
    bf16 lb = __float2bfloat16(b - __bfloat162float(hb));
    __nv_bfloat162 h2; h2.x = ha; h2.y = hb;
    __nv_bfloat162 l2; l2.x = la; l2.y = lb;
    lo = *(uint32_t*)&l2;
    return *(uint32_t*)&h2;
}

// ---------------- conversion kernels ----------------
__global__ void conv_x_kernel(const float* __restrict__ x) {
    int idx = blockIdx.x * 256 + threadIdx.x;          // over MB*1024
    if (idx >= MB * 1024) return;
    int m = idx >> 10, c = idx & 1023;
    float v = x[idx];
    bf16 h = __float2bfloat16(v);
    bf16 l = __float2bfloat16(v - __bfloat162float(h));
    g_xe[(size_t)m * 2048 + c] = h;
    g_xe[(size_t)m * 2048 + 1024 + c] = l;
}

template <int WSEL>
__global__ void conv_w_kernel(const float* __restrict__ W, int N) {
    bf16* dst = WSEL ? g_wpt : g_wat;
    int idx = blockIdx.x * 256 + threadIdx.x;          // over 1024*N
    if (idx >= 1024 * N) return;
    int k = idx / N, n = idx % N;
    float v = W[idx];
    bf16 h = __float2bfloat16(v);
    bf16 l = __float2bfloat16(v - __bfloat162float(h));
    dst[(size_t)n * 2048 + k] = h;
    dst[(size_t)n * 2048 + 1024 + k] = l;
}

// ---------------- bf16x3 GEMM: C(MxN) = A_ext @ B_ext^T, K'=3x1024 ----------------
// MODE 0: A=g_xe,  B=g_wat, C=g_qkv (N=3072)
// MODE 1: A=g_ye,  B=g_wpt, C=out   (N=1024)
template <int MODE, int N>
__global__ __launch_bounds__(256) void gemm_bf16x3(float* __restrict__ Cext) {
    const bf16* A  = MODE ? g_ye  : g_xe;
    const bf16* Bt = MODE ? g_wpt : g_wat;
    float*      C  = MODE ? Cext  : g_qkv;

    __shared__ bf16 As[2][128][40];
    __shared__ bf16 Bs[2][128][40];

    const int tid = threadIdx.x;
    const int m0 = blockIdx.y * 128, n0 = blockIdx.x * 128;
    const int wid = tid >> 5, lane = tid & 31, g = lane >> 2, q = lane & 3;
    const int wm = (wid & 1) * 64, wn = (wid >> 1) * 32;

    float acc[4][4][4];
#pragma unroll
    for (int i = 0; i < 4; i++)
#pragma unroll
        for (int j = 0; j < 4; j++)
#pragma unroll
            for (int r = 0; r < 4; r++) acc[i][j][r] = 0.f;

    const int lrow = tid >> 1;          // 0..127
    const int lp0  = (tid & 1) * 2;     // part base {0,2}

    // prologue: tile 0 (seg 0, kk 0)
#pragma unroll
    for (int c2 = 0; c2 < 2; c2++) {
        int part = lp0 + c2;
        cpa16(&As[0][lrow][part * 8], A  + (size_t)(m0 + lrow) * 2048 + part * 8);
        cpa16(&Bs[0][lrow][part * 8], Bt + (size_t)(n0 + lrow) * 2048 + part * 8);
    }
    cp_commit();

    for (int i = 0; i < 96; i++) {
        cp_wait0();
        __syncthreads();
        if (i + 1 < 96) {
            int seg = (i + 1) >> 5, kk = ((i + 1) & 31) * 32;
            int aoff = ((seg == 2) ? 1024 : 0) + kk;
            int boff = ((seg == 1) ? 1024 : 0) + kk;
            int buf = (i + 1) & 1;
#pragma unroll
            for (int c2 = 0; c2 < 2; c2++) {
                int part = lp0 + c2;
                cpa16(&As[buf][lrow][part * 8], A  + (size_t)(m0 + lrow) * 2048 + aoff + part * 8);
                cpa16(&Bs[buf][lrow][part * 8], Bt + (size_t)(n0 + lrow) * 2048 + boff + part * 8);
            }
            cp_commit();
        }
        int buf = i & 1;
#pragma unroll
        for (int ks = 0; ks < 2; ks++) {
            uint32_t af[4][4];
#pragma unroll
            for (int ma = 0; ma < 4; ma++) {
                int r = wm + ma * 16 + g, c = ks * 16 + 2 * q;
                af[ma][0] = *(const uint32_t*)&As[buf][r][c];
                af[ma][1] = *(const uint32_t*)&As[buf][r + 8][c];
                af[ma][2] = *(const uint32_t*)&As[buf][r][c + 8];
                af[ma][3] = *(const uint32_t*)&As[buf][r + 8][c + 8];
            }
#pragma unroll
            for (int na = 0; na < 4; na++) {
                uint32_t bfg[2];
                int n = wn + na * 8 + g, c = ks * 16 + 2 * q;
                bfg[0] = *(const uint32_t*)&Bs[buf][n][c];
                bfg[1] = *(const uint32_t*)&Bs[buf][n][c + 8];
#pragma unroll
                for (int ma = 0; ma < 4; ma++) mma16816(acc[ma][na], af[ma], bfg);
            }
        }
    }

#pragma unroll
    for (int ma = 0; ma < 4; ma++) {
        int r = m0 + wm + ma * 16 + g;
#pragma unroll
        for (int na = 0; na < 4; na++) {
            int c = n0 + wn + na * 8 + 2 * q;
            *(float2*)&C[(size_t)r * N + c]       = make_float2(acc[ma][na][0], acc[ma][na][1]);
            *(float2*)&C[(size_t)(r + 8) * N + c] = make_float2(acc[ma][na][2], acc[ma][na][3]);
        }
    }
}

// ---------------- RoPE + split + layout kernel ----------------
__global__ void rope_kernel() {
    int idx = blockIdx.x * 256 + threadIdx.x;          // over B*T*H*D = 8.4M
    if (idx >= MB * 1024) return;
    int d = idx & 63, h = (idx >> 6) & 15, t = (idx >> 10) & 2047, b = idx >> 21;

    size_t base = (size_t)(b * TT + t) * 3072 + h * 64;
    float qv = g_qkv[base + d];
    float kv = g_qkv[base + 1024 + d];
    float vv = g_qkv[base + 2048 + d];
    int dro = (d < 32) ? d + 32 : d - 32;
    float qo = g_qkv[base + dro];
    float ko = g_qkv[base + 1024 + dro];
    float sgn = (d < 32) ? -1.f : 1.f;

    int j = d & 31;
    float inv = exp2f(-(float)(2 * j) * (13.287712379549449f / 64.f));
    float ang = (float)t * inv, sn, cs;
    sincosf(ang, &sn, &cs);

    float qr = qv * cs + sgn * qo * sn;
    float kr = kv * cs + sgn * ko * sn;

    int bh = b * 16 + h;
    size_t ob = ((size_t)bh * TT + t) * 128;
    bf16 hh, ll;
    hh = __float2bfloat16(qr); ll = __float2bfloat16(qr - __bfloat162float(hh));
    g_qe[ob + d] = hh; g_qe[ob + 64 + d] = ll;
    hh = __float2bfloat16(kr); ll = __float2bfloat16(kr - __bfloat162float(hh));
    g_ke[ob + d] = hh; g_ke[ob + 64 + d] = ll;
    size_t vb = ((size_t)bh * 64 + d) * (2 * TT);
    hh = __float2bfloat16(vv); ll = __float2bfloat16(vv - __bfloat162float(hh));
    g_vt[vb + t] = hh; g_vt[vb + TT + t] = ll;
}

// ---------------- flash attention, bf16x3 mma ----------------
// block = 256 thr (8 warps), 128 q-rows per block; grid = (T/128, BH)
__global__ __launch_bounds__(256) void attn_kernel() {
    extern __shared__ char smraw[];
    bf16 (*Ks)[64][136] = (bf16(*)[64][136])(smraw);            // [2] double-buffered
    bf16 (*Vs)[64][136] = (bf16(*)[64][136])(smraw + 34816);    // [2]
    bf16 (*Ps)[16][136] = (bf16(*)[16][136])(smraw + 69632);    // [8] per-warp

    const int tid = threadIdx.x, wid = tid >> 5, lane = tid & 31;
    const int g = lane >> 2, q = lane & 3;
    const int bh = blockIdx.y, q0 = blockIdx.x * 128;

    const bf16* qbase = g_qe + ((size_t)bh * TT + q0) * 128;
    const bf16* kbase = g_ke + (size_t)bh * TT * 128;
    const bf16* vbase = g_vt + (size_t)bh * 64 * (2 * TT);

    // persistent Q fragments: 8 k-atoms over [Qhi(64)|Qlo(64)]
    uint32_t qf[8][4];
    {
        int r = wid * 16 + g;
#pragma unroll
        for (int ka = 0; ka < 8; ka++) {
            int c = ka * 16 + 2 * q;
            qf[ka][0] = *(const uint32_t*)&qbase[(size_t)r * 128 + c];
            qf[ka][1] = *(const uint32_t*)&qbase[(size_t)(r + 8) * 128 + c];
            qf[ka][2] = *(const uint32_t*)&qbase[(size_t)r * 128 + c + 8];
            qf[ka][3] = *(const uint32_t*)&qbase[(size_t)(r + 8) * 128 + c + 8];
        }
    }

    float o[8][4];
#pragma unroll
    for (int na = 0; na < 8; na++)
#pragma unroll
        for (int r2 = 0; r2 < 4; r2++) o[na][r2] = 0.f;
    float mrow0 = -1e30f, mrow1 = -1e30f, lr0 = 0.f, lr1 = 0.f;

    const int lrow = tid >> 2;        // 0..63
    const int lp0  = (tid & 3) * 4;   // part base {0,4,8,12}

    // prologue: tile 0
    {
        int j0 = 0;
#pragma unroll
        for (int c2 = 0; c2 < 4; c2++) {
            int part = lp0 + c2;
            cpa16(&Ks[0][lrow][part * 8], kbase + (size_t)(j0 + lrow) * 128 + part * 8);
            const bf16* vsrc = (part < 8)
                ? (vbase + (size_t)lrow * (2 * TT) + j0 + part * 8)
                : (vbase + (size_t)lrow * (2 * TT) + TT + j0 + (part - 8) * 8);
            cpa16(&Vs[0][lrow][part * 8], vsrc);
        }
        cp_commit();
    }

    for (int jt = 0; jt < 32; jt++) {
        cp_wait0();
        __syncthreads();
        if (jt + 1 < 32) {
            int buf2 = (jt + 1) & 1, j0 = (jt + 1) * 64;
#pragma unroll
            for (int c2 = 0; c2 < 4; c2++) {
                int part = lp0 + c2;
                cpa16(&Ks[buf2][lrow][part * 8], kbase + (size_t)(j0 + lrow) * 128 + part * 8);
                const bf16* vsrc = (part < 8)
                    ? (vbase + (size_t)lrow * (2 * TT) + j0 + part * 8)
                    : (vbase + (size_t)lrow * (2 * TT) + TT + j0 + (part - 8) * 8);
                cpa16(&Vs[buf2][lrow][part * 8], vsrc);
            }
            cp_commit();
        }
        int buf = jt & 1;

        // ---- S = Q @ K^T (bf16x3) ----
        float s[8][4];
#pragma unroll
        for (int na = 0; na < 8; na++)
#pragma unroll
            for (int r2 = 0; r2 < 4; r2++) s[na][r2] = 0.f;

#pragma unroll
        for (int seg = 0; seg < 3; seg++) {
            int qab = (seg == 2) ? 4 : 0, kco = (seg == 1) ? 64 : 0;
#pragma unroll
            for (int ks = 0; ks < 4; ks++) {
                int ka = qab + ks, col = kco + ks * 16 + 2 * q;
#pragma unroll
                for (int na = 0; na < 8; na++) {
                    uint32_t bfg[2];
                    bfg[0] = *(const uint32_t*)&Ks[buf][na * 8 + g][col];
                    bfg[1] = *(const uint32_t*)&Ks[buf][na * 8 + g][col + 8];
                    mma16816(s[na], qf[ka], bfg);
                }
            }
        }

        // ---- online softmax ----
        float nm0 = mrow0, nm1 = mrow1;
#pragma unroll
        for (int na = 0; na < 8; na++) {
#pragma unroll
            for (int r2 = 0; r2 < 4; r2++) s[na][r2] *= 0.125f;
            nm0 = fmaxf(nm0, fmaxf(s[na][0], s[na][1]));
            nm1 = fmaxf(nm1, fmaxf(s[na][2], s[na][3]));
        }
        nm0 = fmaxf(nm0, __shfl_xor_sync(0xffffffffu, nm0, 1));
        nm0 = fmaxf(nm0, __shfl_xor_sync(0xffffffffu, nm0, 2));
        nm1 = fmaxf(nm1, __shfl_xor_sync(0xffffffffu, nm1, 1));
        nm1 = fmaxf(nm1, __shfl_xor_sync(0xffffffffu, nm1, 2));
        float corr0 = __expf(mrow0 - nm0), corr1 = __expf(mrow1 - nm1);
        mrow0 = nm0; mrow1 = nm1;
        lr0 *= corr0; lr1 *= corr1;
#pragma unroll
        for (int na = 0; na < 8; na++) {
            o[na][0] *= corr0; o[na][1] *= corr0;
            o[na][2] *= corr1; o[na][3] *= corr1;
        }
#pragma unroll
        for (int na = 0; na < 8; na++) {
            float p0 = __expf(s[na][0] - nm0), p1 = __expf(s[na][1] - nm0);
            float p2 = __expf(s[na][2] - nm1), p3 = __expf(s[na][3] - nm1);
            lr0 += p0 + p1; lr1 += p2 + p3;
            uint32_t lo0, hi0 = pack_hi_lo(p0, p1, lo0);
            uint32_t lo1, hi1 = pack_hi_lo(p2, p3, lo1);
            *(uint32_t*)&Ps[wid][g][na * 8 + 2 * q]          = hi0;
            *(uint32_t*)&Ps[wid][g][64 + na * 8 + 2 * q]     = lo0;
            *(uint32_t*)&Ps[wid][g + 8][na * 8 + 2 * q]      = hi1;
            *(uint32_t*)&Ps[wid][g + 8][64 + na * 8 + 2 * q] = lo1;
        }
        __syncwarp();

        // ---- O += P @ V (bf16x3) ----
#pragma unroll
        for (int seg = 0; seg < 3; seg++) {
            int pco = (seg == 2) ? 64 : 0, vco = (seg == 1) ? 64 : 0;
#pragma unroll
            for (int ks = 0; ks < 4; ks++) {
                uint32_t af[4];
                int pc = pco + ks * 16 + 2 * q;
                af[0] = *(const uint32_t*)&Ps[wid][g][pc];
                af[1] = *(const uint32_t*)&Ps[wid][g + 8][pc];
                af[2] = *(const uint32_t*)&Ps[wid][g][pc + 8];
                af[3] = *(const uint32_t*)&Ps[wid][g + 8][pc + 8];
                int vc = vco + ks * 16 + 2 * q;
#pragma unroll
                for (int na = 0; na < 8; na++) {
                    uint32_t bfg[2];
                    bfg[0] = *(const uint32_t*)&Vs[buf][na * 8 + g][vc];
                    bfg[1] = *(const uint32_t*)&Vs[buf][na * 8 + g][vc + 8];
                    mma16816(o[na], af, bfg);
                }
            }
        }
        __syncwarp();
    }

    // ---- epilogue: normalize + write split y ----
    lr0 += __shfl_xor_sync(0xffffffffu, lr0, 1);
    lr0 += __shfl_xor_sync(0xffffffffu, lr0, 2);
    lr1 += __shfl_xor_sync(0xffffffffu, lr1, 1);
    lr1 += __shfl_xor_sync(0xffffffffu, lr1, 2);
    float inv0 = 1.f / lr0, inv1 = 1.f / lr1;

    int b = bh >> 4, h = bh & 15;
    int t0 = q0 + wid * 16 + g;
    size_t row0 = (size_t)(b * TT + t0) * 2048;
    size_t row1 = (size_t)(b * TT + t0 + 8) * 2048;
#pragma unroll
    for (int na = 0; na < 8; na++) {
        int c = h * 64 + na * 8 + 2 * q;
        uint32_t lo, hi;
        hi = pack_hi_lo(o[na][0] * inv0, o[na][1] * inv0, lo);
        *(uint32_t*)&g_ye[row0 + c] = hi;
        *(uint32_t*)&g_ye[row0 + 1024 + c] = lo;
        hi = pack_hi_lo(o[na][2] * inv1, o[na][3] * inv1, lo);
        *(uint32_t*)&g_ye[row1 + c] = hi;
        *(uint32_t*)&g_ye[row1 + 1024 + c] = lo;
    }
}

// ---------------- launch ----------------
extern "C" void kernel_launch(void* const* d_in, const int* in_sizes, int n_in,
                              void* d_out, int out_size)
{
    const float* x      = (const float*)d_in[0];
    const float* W_attn = (const float*)d_in[1];
    const float* W_proj = (const float*)d_in[2];
    float* out = (float*)d_out;

    cudaFuncSetAttribute(attn_kernel, cudaFuncAttributeMaxDynamicSharedMemorySize, 104448);

    conv_x_kernel<<<MB * 1024 / 256, 256>>>(x);
    conv_w_kernel<0><<<(1024 * 3072) / 256, 256>>>(W_attn, 3072);
    conv_w_kernel<1><<<(1024 * 1024) / 256, 256>>>(W_proj, 1024);
    gemm_bf16x3<0, 3072><<<dim3(24, 64), 256>>>(nullptr);
    rope_kernel<<<MB * 1024 / 256, 256>>>();
    attn_kernel<<<dim3(16, 64), 256, 104448>>>();
    gemm_bf16x3<1, 1024><<<dim3(8, 64), 256>>>(out);
}

// round 3
// speedup vs baseline: 2.7800x; 1.3257x over previous
#include <cuda_runtime.h>
#include <cuda_bf16.h>
#include <cstdint>

typedef __nv_bfloat16 bf16;

#define MB 8192       // B*T
#define TT 2048
#define BH 64         // B*H

// ---------------- device scratch ----------------
__device__ bf16  g_xe [(size_t)MB * 2048];        // x split   [hi(1024) | lo(1024)] row-major
__device__ bf16  g_wat[(size_t)3072 * 2048];      // W_attn^T split, n-major
__device__ bf16  g_wpt[(size_t)1024 * 2048];      // W_proj^T split, n-major
__device__ float g_qkv[(size_t)MB * 3072];        // qkv fp32
__device__ bf16  g_qe [(size_t)BH * TT * 128];    // Q rope split [hi(64)|lo(64)], pre-scaled
__device__ bf16  g_ke [(size_t)BH * TT * 128];    // K rope split
__device__ bf16  g_vt [(size_t)BH * 64 * 2 * TT]; // V dim-major [hi(T)|lo(T)] per dim
__device__ bf16  g_ye [(size_t)MB * 2048];        // attention out split

// ---------------- helpers ----------------
__device__ __forceinline__ void cpa16(void* s, const void* g) {
    uint32_t sa = (uint32_t)__cvta_generic_to_shared(s);
    asm volatile("cp.async.ca.shared.global [%0], [%1], 16;\n" :: "r"(sa), "l"(g));
}
__device__ __forceinline__ void cp_commit() { asm volatile("cp.async.commit_group;\n"); }
__device__ __forceinline__ void cp_wait0()  { asm volatile("cp.async.wait_group 0;\n"); }
__device__ __forceinline__ void cp_wait2()  { asm volatile("cp.async.wait_group 2;\n"); }

__device__ __forceinline__ void ldsm4(uint32_t* r, const void* p) {
    uint32_t a = (uint32_t)__cvta_generic_to_shared(p);
    asm volatile("ldmatrix.sync.aligned.m8n8.x4.shared.b16 {%0,%1,%2,%3}, [%4];"
                 : "=r"(r[0]), "=r"(r[1]), "=r"(r[2]), "=r"(r[3]) : "r"(a));
}

__device__ __forceinline__ void mma16816(float* c, const uint32_t* a, const uint32_t* b) {
    asm volatile("mma.sync.aligned.m16n8k16.row.col.f32.bf16.bf16.f32 "
        "{%0,%1,%2,%3}, {%4,%5,%6,%7}, {%8,%9}, {%0,%1,%2,%3};"
        : "+f"(c[0]), "+f"(c[1]), "+f"(c[2]), "+f"(c[3])
        : "r"(a[0]), "r"(a[1]), "r"(a[2]), "r"(a[3]), "r"(b[0]), "r"(b[1]));
}

__device__ __forceinline__ float ex2(float x) {
    float y; asm("ex2.approx.f32 %0, %1;" : "=f"(y) : "f"(x)); return y;
}

// split pair (a,b) -> packed hi bf16x2 (return) and lo bf16x2 (out param)
__device__ __forceinline__ uint32_t pack_hi_lo(float a, float b, uint32_t& lo) {
    bf16 ha = __float2bfloat16(a), hb = __float2bfloat16(b);
    bf16 la = __float2bfloat16(a - __bfloat162float(ha));
    bf16 lb = __float2bfloat16(b - __bfloat162float(hb));
    __nv_bfloat162 h2; h2.x = ha; h2.y = hb;
    __nv_bfloat162 l2; l2.x = la; l2.y = lb;
    lo = *(uint32_t*)&l2;
    return *(uint32_t*)&h2;
}

// ---------------- conversion kernels ----------------
__global__ void conv_x_kernel(const float* __restrict__ x) {
    int idx = blockIdx.x * 256 + threadIdx.x;
    if (idx >= MB * 1024) return;
    int m = idx >> 10, c = idx & 1023;
    float v = x[idx];
    bf16 h = __float2bfloat16(v);
    bf16 l = __float2bfloat16(v - __bfloat162float(h));
    g_xe[(size_t)m * 2048 + c] = h;
    g_xe[(size_t)m * 2048 + 1024 + c] = l;
}

// tiled transpose: W[k][n] -> dst[n][ hi k | lo k ]
template <int WSEL>
__global__ void conv_w_kernel(const float* __restrict__ W, int N) {
    bf16* dst = WSEL ? g_wpt : g_wat;
    __shared__ float ws[32][33];
    int n0 = blockIdx.x * 32, k0 = blockIdx.y * 32;
    int tx = threadIdx.x & 31, ty = threadIdx.x >> 5;
#pragma unroll
    for (int i = 0; i < 4; i++) {
        int k = k0 + ty + i * 8;
        ws[ty + i * 8][tx] = W[(size_t)k * N + n0 + tx];
    }
    __syncthreads();
#pragma unroll
    for (int i = 0; i < 4; i++) {
        int n = n0 + ty + i * 8, k = k0 + tx;
        float v = ws[tx][ty + i * 8];
        bf16 h = __float2bfloat16(v);
        bf16 l = __float2bfloat16(v - __bfloat162float(h));
        dst[(size_t)n * 2048 + k] = h;
        dst[(size_t)n * 2048 + 1024 + k] = l;
    }
}

// ---------------- bf16x3 GEMM: C(MxN) = A_ext @ B_ext^T, 96 K-tiles of 32 ----------------
template <int MODE, int N>
__global__ __launch_bounds__(256) void gemm_bf16x3(float* __restrict__ Cext) {
    const bf16* A  = MODE ? g_ye  : g_xe;
    const bf16* Bt = MODE ? g_wpt : g_wat;
    float*      C  = MODE ? Cext  : g_qkv;

    extern __shared__ bf16 sm[];   // 4 stages x (As 128x40 + Bs 128x40)

    const int tid = threadIdx.x;
    const int m0 = blockIdx.y * 128, n0 = blockIdx.x * 128;
    const int wid = tid >> 5, lane = tid & 31, g = lane >> 2, q = lane & 3;
    const int wm = (wid & 1) * 64, wn = (wid >> 1) * 32;

    // ldmatrix lane address mappings
    const int arow = (lane & 7) + ((lane >> 3) & 1) * 8;
    const int acs  = (lane >> 4) * 8;
    const int brow = (lane & 7) + (lane >> 4) * 8;
    const int bcs  = ((lane >> 3) & 1) * 8;

    float acc[4][4][4];
#pragma unroll
    for (int i = 0; i < 4; i++)
#pragma unroll
        for (int j = 0; j < 4; j++)
#pragma unroll
            for (int r = 0; r < 4; r++) acc[i][j][r] = 0.f;

    const int lrow = tid >> 1;
    const int lp0  = (tid & 1) * 2;

    auto load_tile = [&](int t, int stage) {
        int seg = t >> 5, kk = (t & 31) * 32;
        int aoff = ((seg == 2) ? 1024 : 0) + kk;
        int boff = ((seg == 1) ? 1024 : 0) + kk;
        bf16 (*As)[40] = (bf16(*)[40])(sm + stage * 10240);
        bf16 (*Bs)[40] = (bf16(*)[40])(sm + stage * 10240 + 5120);
#pragma unroll
        for (int c2 = 0; c2 < 2; c2++) {
            int part = lp0 + c2;
            cpa16(&As[lrow][part * 8], A  + (size_t)(m0 + lrow) * 2048 + aoff + part * 8);
            cpa16(&Bs[lrow][part * 8], Bt + (size_t)(n0 + lrow) * 2048 + boff + part * 8);
        }
    };

    // prologue: 3 tiles in flight
    load_tile(0, 0); cp_commit();
    load_tile(1, 1); cp_commit();
    load_tile(2, 2); cp_commit();

    for (int i = 0; i < 96; i++) {
        cp_wait2();
        __syncthreads();
        if (i + 3 < 96) load_tile(i + 3, (i + 3) & 3);
        cp_commit();

        bf16 (*As)[40] = (bf16(*)[40])(sm + (i & 3) * 10240);
        bf16 (*Bs)[40] = (bf16(*)[40])(sm + (i & 3) * 10240 + 5120);
#pragma unroll
        for (int ks = 0; ks < 2; ks++) {
            const int c0 = ks * 16;
            uint32_t af[4][4];
#pragma unroll
            for (int ma = 0; ma < 4; ma++)
                ldsm4(af[ma], &As[wm + ma * 16 + arow][c0 + acs]);
            uint32_t bf4[2][4];
            ldsm4(bf4[0], &Bs[wn + 0  + brow][c0 + bcs]);
            ldsm4(bf4[1], &Bs[wn + 16 + brow][c0 + bcs]);
#pragma unroll
            for (int na = 0; na < 4; na++) {
                const uint32_t* bb = &bf4[na >> 1][(na & 1) * 2];
#pragma unroll
                for (int ma = 0; ma < 4; ma++) mma16816(acc[ma][na], af[ma], bb);
            }
        }
        __syncthreads();
    }

#pragma unroll
    for (int ma = 0; ma < 4; ma++) {
        int r = m0 + wm + ma * 16 + g;
#pragma unroll
        for (int na = 0; na < 4; na++) {
            int c = n0 + wn + na * 8 + 2 * q;
            *(float2*)&C[(size_t)r * N + c]       = make_float2(acc[ma][na][0], acc[ma][na][1]);
            *(float2*)&C[(size_t)(r + 8) * N + c] = make_float2(acc[ma][na][2], acc[ma][na][3]);
        }
    }
}

// ---------------- RoPE (Q,K only); Q pre-scaled by 0.125*log2(e) ----------------
__global__ void rope_kernel() {
    int idx = blockIdx.x * 256 + threadIdx.x;
    if (idx >= MB * 1024) return;
    int d = idx & 63, h = (idx >> 6) & 15, t = (idx >> 10) & 2047, b = idx >> 21;

    size_t base = (size_t)(b * TT + t) * 3072 + h * 64;
    float qv = g_qkv[base + d];
    float kv = g_qkv[base + 1024 + d];
    int dro = (d < 32) ? d + 32 : d - 32;
    float qo = g_qkv[base + dro];
    float ko = g_qkv[base + 1024 + dro];
    float sgn = (d < 32) ? -1.f : 1.f;

    int j = d & 31;
    float inv = exp2f(-(float)(2 * j) * (13.287712379549449f / 64.f));
    float ang = (float)t * inv, sn, cs;
    sincosf(ang, &sn, &cs);

    float qr = (qv * cs + sgn * qo * sn) * 0.18033688011112043f;  // 1/8 * log2(e)
    float kr = kv * cs + sgn * ko * sn;

    int bh = b * 16 + h;
    size_t ob = ((size_t)bh * TT + t) * 128;
    bf16 hh, ll;
    hh = __float2bfloat16(qr); ll = __float2bfloat16(qr - __bfloat162float(hh));
    g_qe[ob + d] = hh; g_qe[ob + 64 + d] = ll;
    hh = __float2bfloat16(kr); ll = __float2bfloat16(kr - __bfloat162float(hh));
    g_ke[ob + d] = hh; g_ke[ob + 64 + d] = ll;
}

// ---------------- V transpose to dim-major split ----------------
__global__ void vtrans_kernel() {
    __shared__ float vs[32][65];
    int bh = blockIdx.y, t0 = blockIdx.x * 32;
    int b = bh >> 4, h = bh & 15;
    int tid = threadIdx.x;
#pragma unroll
    for (int i = 0; i < 8; i++) {
        int idx = i * 256 + tid;
        int t = idx >> 6, d = idx & 63;
        vs[t][d] = g_qkv[(size_t)(b * TT + t0 + t) * 3072 + 2048 + h * 64 + d];
    }
    __syncthreads();
    int t = tid & 31;
#pragma unroll
    for (int i = 0; i < 8; i++) {
        int d = i * 8 + (tid >> 5);
        float v = vs[t][d];
        bf16 hh = __float2bfloat16(v);
        bf16 ll = __float2bfloat16(v - __bfloat162float(hh));
        size_t vb = ((size_t)bh * 64 + d) * (2 * TT) + t0 + t;
        g_vt[vb] = hh;
        g_vt[vb + TT] = ll;
    }
}

// ---------------- flash attention, bf16x3 mma, register-resident P ----------------
// block = 256 thr (8 warps), 128 q-rows per block; grid = (T/128, BH)
__global__ __launch_bounds__(256) void attn_kernel() {
    extern __shared__ char smraw[];
    bf16 (*Ks)[64][136] = (bf16(*)[64][136])(smraw);            // [2] stages
    bf16 (*Vs)[64][136] = (bf16(*)[64][136])(smraw + 34816);    // [2] stages

    const int tid = threadIdx.x, wid = tid >> 5, lane = tid & 31;
    const int g = lane >> 2, q = lane & 3;
    const int bh = blockIdx.y, q0 = blockIdx.x * 128;

    const int krow = (lane & 7) + (lane >> 4) * 8;      // B-pattern ldmatrix row
    const int kcs  = ((lane >> 3) & 1) * 8;

    const bf16* qbase = g_qe + ((size_t)bh * TT + q0) * 128;
    const bf16* kbase = g_ke + (size_t)bh * TT * 128;
    const bf16* vbase = g_vt + (size_t)bh * 64 * (2 * TT);

    // persistent Q fragments: 8 k-atoms over [Qhi(64)|Qlo(64)]
    uint32_t qf[8][4];
    {
        int r = wid * 16 + g;
#pragma unroll
        for (int ka = 0; ka < 8; ka++) {
            int c = ka * 16 + 2 * q;
            qf[ka][0] = *(const uint32_t*)&qbase[(size_t)r * 128 + c];
            qf[ka][1] = *(const uint32_t*)&qbase[(size_t)(r + 8) * 128 + c];
            qf[ka][2] = *(const uint32_t*)&qbase[(size_t)r * 128 + c + 8];
            qf[ka][3] = *(const uint32_t*)&qbase[(size_t)(r + 8) * 128 + c + 8];
        }
    }

    float o[8][4];
#pragma unroll
    for (int na = 0; na < 8; na++)
#pragma unroll
        for (int r2 = 0; r2 < 4; r2++) o[na][r2] = 0.f;
    float mrow0 = -1e30f, mrow1 = -1e30f, lr0 = 0.f, lr1 = 0.f;

    const int lrow = tid >> 2;
    const int lp0  = (tid & 3) * 4;

    auto load_tile = [&](int jt, int buf) {
        int j0 = jt * 64;
#pragma unroll
        for (int c2 = 0; c2 < 4; c2++) {
            int part = lp0 + c2;
            cpa16(&Ks[buf][lrow][part * 8], kbase + (size_t)(j0 + lrow) * 128 + part * 8);
            const bf16* vsrc = (part < 8)
                ? (vbase + (size_t)lrow * (2 * TT) + j0 + part * 8)
                : (vbase + (size_t)lrow * (2 * TT) + TT + j0 + (part - 8) * 8);
            cpa16(&Vs[buf][lrow][part * 8], vsrc);
        }
        cp_commit();
    };

    load_tile(0, 0);

    for (int jt = 0; jt < 32; jt++) {
        cp_wait0();
        __syncthreads();
        if (jt + 1 < 32) load_tile(jt + 1, (jt + 1) & 1);
        const int buf = jt & 1;

        // ---- S = Q @ K^T (bf16x3), already in log2-domain with 1/sqrt(D) folded ----
        float s[8][4];
#pragma unroll
        for (int na = 0; na < 8; na++)
#pragma unroll
            for (int r2 = 0; r2 < 4; r2++) s[na][r2] = 0.f;

#pragma unroll
        for (int seg = 0; seg < 3; seg++) {
            const int qab = (seg == 2) ? 4 : 0, kco = (seg == 1) ? 64 : 0;
#pragma unroll
            for (int ks = 0; ks < 4; ks++) {
                const int ka = qab + ks, c0 = kco + ks * 16;
#pragma unroll
                for (int pr = 0; pr < 4; pr++) {
                    uint32_t b4[4];
                    ldsm4(b4, &Ks[buf][pr * 16 + krow][c0 + kcs]);
                    mma16816(s[2 * pr],     qf[ka], b4);
                    mma16816(s[2 * pr + 1], qf[ka], b4 + 2);
                }
            }
        }

        // ---- online softmax (log2 domain) ----
        float nm0 = mrow0, nm1 = mrow1;
#pragma unroll
        for (int na = 0; na < 8; na++) {
            nm0 = fmaxf(nm0, fmaxf(s[na][0], s[na][1]));
            nm1 = fmaxf(nm1, fmaxf(s[na][2], s[na][3]));
        }
        nm0 = fmaxf(nm0, __shfl_xor_sync(0xffffffffu, nm0, 1));
        nm0 = fmaxf(nm0, __shfl_xor_sync(0xffffffffu, nm0, 2));
        nm1 = fmaxf(nm1, __shfl_xor_sync(0xffffffffu, nm1, 1));
        nm1 = fmaxf(nm1, __shfl_xor_sync(0xffffffffu, nm1, 2));
        float corr0 = ex2(mrow0 - nm0), corr1 = ex2(mrow1 - nm1);
        mrow0 = nm0; mrow1 = nm1;
        lr0 *= corr0; lr1 *= corr1;
#pragma unroll
        for (int na = 0; na < 8; na++) {
            o[na][0] *= corr0; o[na][1] *= corr0;
            o[na][2] *= corr1; o[na][3] *= corr1;
        }

        // ---- P in registers, directly in A-fragment layout ----
        uint32_t phA[8], phB[8], plA[8], plB[8];
#pragma unroll
        for (int na = 0; na < 8; na++) {
            float p0 = ex2(s[na][0] - nm0), p1 = ex2(s[na][1] - nm0);
            float p2 = ex2(s[na][2] - nm1), p3 = ex2(s[na][3] - nm1);
            lr0 += p0 + p1; lr1 += p2 + p3;
            phA[na] = pack_hi_lo(p0, p1, plA[na]);
            phB[na] = pack_hi_lo(p2, p3, plB[na]);
        }

        // ---- O += P @ V (bf16x3) ----
#pragma unroll
        for (int seg = 0; seg < 3; seg++) {
            const uint32_t* PA = (seg == 2) ? plA : phA;
            const uint32_t* PB = (seg == 2) ? plB : phB;
            const int vco = (seg == 1) ? 64 : 0;
#pragma unroll
            for (int ks = 0; ks < 4; ks++) {
                const int c0 = vco + ks * 16;
                uint32_t af[4] = { PA[2 * ks], PB[2 * ks], PA[2 * ks + 1], PB[2 * ks + 1] };
#pragma unroll
                for (int pr = 0; pr < 4; pr++) {
                    uint32_t b4[4];
                    ldsm4(b4, &Vs[buf][pr * 16 + krow][c0 + kcs]);
                    mma16816(o[2 * pr],     af, b4);
                    mma16816(o[2 * pr + 1], af, b4 + 2);
                }
            }
        }
    }

    // ---- epilogue: normalize + write split y ----
    lr0 += __shfl_xor_sync(0xffffffffu, lr0, 1);
    lr0 += __shfl_xor_sync(0xffffffffu, lr0, 2);
    lr1 += __shfl_xor_sync(0xffffffffu, lr1, 1);
    lr1 += __shfl_xor_sync(0xffffffffu, lr1, 2);
    float inv0 = 1.f / lr0, inv1 = 1.f / lr1;

    int b = bh >> 4, h = bh & 15;
    int t0 = q0 + wid * 16 + g;
    size_t row0 = (size_t)(b * TT + t0) * 2048;
    size_t row1 = (size_t)(b * TT + t0 + 8) * 2048;
#pragma unroll
    for (int na = 0; na < 8; na++) {
        int c = h * 64 + na * 8 + 2 * q;
        uint32_t lo, hi;
        hi = pack_hi_lo(o[na][0] * inv0, o[na][1] * inv0, lo);
        *(uint32_t*)&g_ye[row0 + c] = hi;
        *(uint32_t*)&g_ye[row0 + 1024 + c] = lo;
        hi = pack_hi_lo(o[na][2] * inv1, o[na][3] * inv1, lo);
        *(uint32_t*)&g_ye[row1 + c] = hi;
        *(uint32_t*)&g_ye[row1 + 1024 + c] = lo;
    }
}

// ---------------- launch ----------------
extern "C" void kernel_launch(void* const* d_in, const int* in_sizes, int n_in,
                              void* d_out, int out_size)
{
    const float* x      = (const float*)d_in[0];
    const float* W_attn = (const float*)d_in[1];
    const float* W_proj = (const float*)d_in[2];
    float* out = (float*)d_out;

    cudaFuncSetAttribute(gemm_bf16x3<0, 3072>, cudaFuncAttributeMaxDynamicSharedMemorySize, 81920);
    cudaFuncSetAttribute(gemm_bf16x3<1, 1024>, cudaFuncAttributeMaxDynamicSharedMemorySize, 81920);
    cudaFuncSetAttribute(attn_kernel, cudaFuncAttributeMaxDynamicSharedMemorySize, 69632);

    conv_x_kernel<<<MB * 1024 / 256, 256>>>(x);
    conv_w_kernel<0><<<dim3(96, 32), 256>>>(W_attn, 3072);
    conv_w_kernel<1><<<dim3(32, 32), 256>>>(W_proj, 1024);
    gemm_bf16x3<0, 3072><<<dim3(24, 64), 256, 81920>>>(nullptr);
    rope_kernel<<<MB * 1024 / 256, 256>>>();
    vtrans_kernel<<<dim3(64, 64), 256>>>();
    attn_kernel<<<dim3(16, 64), 256, 69632>>>();
    gemm_bf16x3<1, 1024><<<dim3(8, 64), 256, 81920>>>(out);
}

// round 4
// speedup vs baseline: 3.0240x; 1.0878x over previous
#include <cuda_runtime.h>
#include <cuda_bf16.h>
#include <cstdint>

typedef __nv_bfloat16 bf16;

#define MB 8192       // B*T
#define TT 2048
#define BH 64         // B*H

// ---------------- device scratch ----------------
__device__ bf16  g_xe [(size_t)MB * 2048];        // x split   [hi(1024) | lo(1024)] row-major
__device__ bf16  g_wat[(size_t)3072 * 2048];      // W_attn^T split, n-major
__device__ bf16  g_wpt[(size_t)1024 * 2048];      // W_proj^T split, n-major
__device__ float g_qkv[(size_t)MB * 3072];        // qkv fp32
__device__ bf16  g_qe [(size_t)BH * TT * 128];    // Q rope split [hi(64)|lo(64)], pre-scaled
__device__ bf16  g_ke [(size_t)BH * TT * 128];    // K rope split
__device__ bf16  g_vt [(size_t)BH * 64 * 2 * TT]; // V dim-major [hi(T)|lo(T)] per dim
__device__ bf16  g_ye [(size_t)MB * 2048];        // attention out split

// ---------------- helpers ----------------
__device__ __forceinline__ void cpa16(void* s, const void* g) {
    uint32_t sa = (uint32_t)__cvta_generic_to_shared(s);
    asm volatile("cp.async.ca.shared.global [%0], [%1], 16;\n" :: "r"(sa), "l"(g));
}
__device__ __forceinline__ void cp_commit() { asm volatile("cp.async.commit_group;\n"); }
__device__ __forceinline__ void cp_wait1()  { asm volatile("cp.async.wait_group 1;\n"); }
__device__ __forceinline__ void cp_wait2()  { asm volatile("cp.async.wait_group 2;\n"); }

__device__ __forceinline__ void ldsm4(uint32_t* r, const void* p) {
    uint32_t a = (uint32_t)__cvta_generic_to_shared(p);
    asm volatile("ldmatrix.sync.aligned.m8n8.x4.shared.b16 {%0,%1,%2,%3}, [%4];"
                 : "=r"(r[0]), "=r"(r[1]), "=r"(r[2]), "=r"(r[3]) : "r"(a));
}

__device__ __forceinline__ void mma16816(float* c, const uint32_t* a, const uint32_t* b) {
    asm volatile("mma.sync.aligned.m16n8k16.row.col.f32.bf16.bf16.f32 "
        "{%0,%1,%2,%3}, {%4,%5,%6,%7}, {%8,%9}, {%0,%1,%2,%3};"
        : "+f"(c[0]), "+f"(c[1]), "+f"(c[2]), "+f"(c[3])
        : "r"(a[0]), "r"(a[1]), "r"(a[2]), "r"(a[3]), "r"(b[0]), "r"(b[1]));
}

__device__ __forceinline__ float ex2(float x) {
    float y; asm("ex2.approx.f32 %0, %1;" : "=f"(y) : "f"(x)); return y;
}

__device__ __forceinline__ uint32_t pack_hi_lo(float a, float b, uint32_t& lo) {
    bf16 ha = __float2bfloat16(a), hb = __float2bfloat16(b);
    bf16 la = __float2bfloat16(a - __bfloat162float(ha));
    bf16 lb = __float2bfloat16(b - __bfloat162float(hb));
    __nv_bfloat162 h2; h2.x = ha; h2.y = hb;
    __nv_bfloat162 l2; l2.x = la; l2.y = lb;
    lo = *(uint32_t*)&l2;
    return *(uint32_t*)&h2;
}

// ---------------- conversion kernels ----------------
__global__ void conv_x_kernel(const float* __restrict__ x) {
    int idx = blockIdx.x * 256 + threadIdx.x;
    if (idx >= MB * 1024) return;
    int m = idx >> 10, c = idx & 1023;
    float v = x[idx];
    bf16 h = __float2bfloat16(v);
    bf16 l = __float2bfloat16(v - __bfloat162float(h));
    g_xe[(size_t)m * 2048 + c] = h;
    g_xe[(size_t)m * 2048 + 1024 + c] = l;
}

template <int WSEL>
__global__ void conv_w_kernel(const float* __restrict__ W, int N) {
    bf16* dst = WSEL ? g_wpt : g_wat;
    __shared__ float ws[32][33];
    int n0 = blockIdx.x * 32, k0 = blockIdx.y * 32;
    int tx = threadIdx.x & 31, ty = threadIdx.x >> 5;
#pragma unroll
    for (int i = 0; i < 4; i++) {
        int k = k0 + ty + i * 8;
        ws[ty + i * 8][tx] = W[(size_t)k * N + n0 + tx];
    }
    __syncthreads();
#pragma unroll
    for (int i = 0; i < 4; i++) {
        int n = n0 + ty + i * 8, k = k0 + tx;
        float v = ws[tx][ty + i * 8];
        bf16 h = __float2bfloat16(v);
        bf16 l = __float2bfloat16(v - __bfloat162float(h));
        dst[(size_t)n * 2048 + k] = h;
        dst[(size_t)n * 2048 + 1024 + k] = l;
    }
}

// ---------------- bf16x3 GEMM, segment-fused: 64 k16 steps, 4-stage pipeline ----------------
// smem per stage: Ahi/Alo/Bhi/Blo, each 128x16 (+8 pad) bf16
#define GST 12288   // bf16 elems per stage: 4 * 128 * 24
template <int MODE, int N>
__global__ __launch_bounds__(256, 2) void gemm_bf16x3(float* __restrict__ Cext) {
    const bf16* A  = MODE ? g_ye  : g_xe;
    const bf16* Bt = MODE ? g_wpt : g_wat;
    float*      C  = MODE ? Cext  : g_qkv;

    extern __shared__ bf16 sm[];   // 4 stages x GST

    const int tid = threadIdx.x;
    const int m0 = blockIdx.y * 128, n0 = blockIdx.x * 128;
    const int wid = tid >> 5, lane = tid & 31, g = lane >> 2, q = lane & 3;
    const int wm = (wid & 1) * 64, wn = (wid >> 1) * 32;

    const int arow = (lane & 7) + ((lane >> 3) & 1) * 8;
    const int acs  = (lane >> 4) * 8;
    const int brow = (lane & 7) + (lane >> 4) * 8;
    const int bcs  = ((lane >> 3) & 1) * 8;

    float acc[4][4][4];
#pragma unroll
    for (int i = 0; i < 4; i++)
#pragma unroll
        for (int j = 0; j < 4; j++)
#pragma unroll
            for (int r = 0; r < 4; r++) acc[i][j][r] = 0.f;

    const int lrow = tid >> 1;          // 0..127
    const int lhalf = (tid & 1) * 8;    // which 16B of the 32B row

    auto load_tile = [&](int t, int stage) {
        const int kk = t * 16;
        bf16* st = sm + stage * GST;
        const bf16* arow_p = A  + (size_t)(m0 + lrow) * 2048 + kk + lhalf;
        const bf16* brow_p = Bt + (size_t)(n0 + lrow) * 2048 + kk + lhalf;
        cpa16(st +        lrow * 24 + lhalf, arow_p);          // Ahi
        cpa16(st + 3072 + lrow * 24 + lhalf, arow_p + 1024);   // Alo
        cpa16(st + 6144 + lrow * 24 + lhalf, brow_p);          // Bhi
        cpa16(st + 9216 + lrow * 24 + lhalf, brow_p + 1024);   // Blo
        cp_commit();
    };

    load_tile(0, 0);
    load_tile(1, 1);
    load_tile(2, 2);

    for (int i = 0; i < 64; i++) {
        cp_wait2();
        __syncthreads();
        if (i + 3 < 64) load_tile(i + 3, (i + 3) & 3);
        else cp_commit();

        const bf16* st = sm + (i & 3) * GST;
        const bf16 (*Ah)[24] = (const bf16(*)[24])(st);
        const bf16 (*Al)[24] = (const bf16(*)[24])(st + 3072);
        const bf16 (*Bh)[24] = (const bf16(*)[24])(st + 6144);
        const bf16 (*Bl)[24] = (const bf16(*)[24])(st + 9216);

        uint32_t ah[4][4], al[4][4], bh[2][4], bl[2][4];
#pragma unroll
        for (int ma = 0; ma < 4; ma++) ldsm4(ah[ma], &Ah[wm + ma * 16 + arow][acs]);
        ldsm4(bh[0], &Bh[wn + 0  + brow][bcs]);
        ldsm4(bh[1], &Bh[wn + 16 + brow][bcs]);
        ldsm4(bl[0], &Bl[wn + 0  + brow][bcs]);
        ldsm4(bl[1], &Bl[wn + 16 + brow][bcs]);
#pragma unroll
        for (int ma = 0; ma < 4; ma++) ldsm4(al[ma], &Al[wm + ma * 16 + arow][acs]);

#pragma unroll
        for (int na = 0; na < 4; na++) {
            const uint32_t* bbh = &bh[na >> 1][(na & 1) * 2];
            const uint32_t* bbl = &bl[na >> 1][(na & 1) * 2];
#pragma unroll
            for (int ma = 0; ma < 4; ma++) {
                mma16816(acc[ma][na], ah[ma], bbh);   // Ahi*Bhi
                mma16816(acc[ma][na], ah[ma], bbl);   // Ahi*Blo
                mma16816(acc[ma][na], al[ma], bbh);   // Alo*Bhi
            }
        }
        __syncthreads();
    }

#pragma unroll
    for (int ma = 0; ma < 4; ma++) {
        int r = m0 + wm + ma * 16 + g;
#pragma unroll
        for (int na = 0; na < 4; na++) {
            int c = n0 + wn + na * 8 + 2 * q;
            *(float2*)&C[(size_t)r * N + c]       = make_float2(acc[ma][na][0], acc[ma][na][1]);
            *(float2*)&C[(size_t)(r + 8) * N + c] = make_float2(acc[ma][na][2], acc[ma][na][3]);
        }
    }
}

// ---------------- RoPE (Q,K only); Q pre-scaled by 0.125*log2(e) ----------------
__global__ void rope_kernel() {
    int idx = blockIdx.x * 256 + threadIdx.x;
    if (idx >= MB * 1024) return;
    int d = idx & 63, h = (idx >> 6) & 15, t = (idx >> 10) & 2047, b = idx >> 21;

    size_t base = (size_t)(b * TT + t) * 3072 + h * 64;
    float qv = g_qkv[base + d];
    float kv = g_qkv[base + 1024 + d];
    int dro = (d < 32) ? d + 32 : d - 32;
    float qo = g_qkv[base + dro];
    float ko = g_qkv[base + 1024 + dro];
    float sgn = (d < 32) ? -1.f : 1.f;

    int j = d & 31;
    float inv = exp2f(-(float)(2 * j) * (13.287712379549449f / 64.f));
    float ang = (float)t * inv, sn, cs;
    sincosf(ang, &sn, &cs);

    float qr = (qv * cs + sgn * qo * sn) * 0.18033688011112043f;  // 1/8 * log2(e)
    float kr = kv * cs + sgn * ko * sn;

    int bh = b * 16 + h;
    size_t ob = ((size_t)bh * TT + t) * 128;
    bf16 hh, ll;
    hh = __float2bfloat16(qr); ll = __float2bfloat16(qr - __bfloat162float(hh));
    g_qe[ob + d] = hh; g_qe[ob + 64 + d] = ll;
    hh = __float2bfloat16(kr); ll = __float2bfloat16(kr - __bfloat162float(hh));
    g_ke[ob + d] = hh; g_ke[ob + 64 + d] = ll;
}

// ---------------- V transpose to dim-major split ----------------
__global__ void vtrans_kernel() {
    __shared__ float vs[32][65];
    int bh = blockIdx.y, t0 = blockIdx.x * 32;
    int b = bh >> 4, h = bh & 15;
    int tid = threadIdx.x;
#pragma unroll
    for (int i = 0; i < 8; i++) {
        int idx = i * 256 + tid;
        int t = idx >> 6, d = idx & 63;
        vs[t][d] = g_qkv[(size_t)(b * TT + t0 + t) * 3072 + 2048 + h * 64 + d];
    }
    __syncthreads();
    int t = tid & 31;
#pragma unroll
    for (int i = 0; i < 8; i++) {
        int d = i * 8 + (tid >> 5);
        float v = vs[t][d];
        bf16 hh = __float2bfloat16(v);
        bf16 ll = __float2bfloat16(v - __bfloat162float(hh));
        size_t vb = ((size_t)bh * 64 + d) * (2 * TT) + t0 + t;
        g_vt[vb] = hh;
        g_vt[vb + TT] = ll;
    }
}

// ---------------- flash attention, bf16x3 mma, segment-fused, 3-stage ----------------
// block = 256 thr (8 warps), 128 q-rows per block; grid = (T/128, BH)
#define AST 34816   // bytes per stage (Ks 64x136 + Vs 64x136, bf16)
__global__ __launch_bounds__(256) void attn_kernel() {
    extern __shared__ char smraw[];

    const int tid = threadIdx.x, wid = tid >> 5, lane = tid & 31;
    const int g = lane >> 2, q = lane & 3;
    const int bh = blockIdx.y, q0 = blockIdx.x * 128;

    const int krow = (lane & 7) + (lane >> 4) * 8;
    const int kcs  = ((lane >> 3) & 1) * 8;

    const bf16* qbase = g_qe + ((size_t)bh * TT + q0) * 128;
    const bf16* kbase = g_ke + (size_t)bh * TT * 128;
    const bf16* vbase = g_vt + (size_t)bh * 64 * (2 * TT);

    // persistent Q fragments: qf[0..3]=hi k-atoms, qf[4..7]=lo
    uint32_t qf[8][4];
    {
        int r = wid * 16 + g;
#pragma unroll
        for (int ka = 0; ka < 8; ka++) {
            int c = ka * 16 + 2 * q;
            qf[ka][0] = *(const uint32_t*)&qbase[(size_t)r * 128 + c];
            qf[ka][1] = *(const uint32_t*)&qbase[(size_t)(r + 8) * 128 + c];
            qf[ka][2] = *(const uint32_t*)&qbase[(size_t)r * 128 + c + 8];
            qf[ka][3] = *(const uint32_t*)&qbase[(size_t)(r + 8) * 128 + c + 8];
        }
    }

    float o[8][4];
#pragma unroll
    for (int na = 0; na < 8; na++)
#pragma unroll
        for (int r2 = 0; r2 < 4; r2++) o[na][r2] = 0.f;
    float mrow0 = -1e30f, mrow1 = -1e30f, lr0 = 0.f, lr1 = 0.f;

    const int lrow = tid >> 2;
    const int lp0  = (tid & 3) * 4;

    auto load_tile = [&](int jt, int buf) {
        bf16 (*Ks)[136] = (bf16(*)[136])(smraw + buf * AST);
        bf16 (*Vs)[136] = (bf16(*)[136])(smraw + buf * AST + 17408);
        int j0 = jt * 64;
#pragma unroll
        for (int c2 = 0; c2 < 4; c2++) {
            int part = lp0 + c2;
            cpa16(&Ks[lrow][part * 8], kbase + (size_t)(j0 + lrow) * 128 + part * 8);
            const bf16* vsrc = (part < 8)
                ? (vbase + (size_t)lrow * (2 * TT) + j0 + part * 8)
                : (vbase + (size_t)lrow * (2 * TT) + TT + j0 + (part - 8) * 8);
            cpa16(&Vs[lrow][part * 8], vsrc);
        }
        cp_commit();
    };

    load_tile(0, 0);
    load_tile(1, 1);

    for (int jt = 0; jt < 32; jt++) {
        cp_wait1();
        __syncthreads();
        if (jt + 2 < 32) load_tile(jt + 2, (jt + 2) % 3);
        else cp_commit();

        const int buf = jt % 3;
        const bf16 (*Ks)[136] = (const bf16(*)[136])(smraw + buf * AST);
        const bf16 (*Vs)[136] = (const bf16(*)[136])(smraw + buf * AST + 17408);

        // ---- S = Qhi*Khi + Qhi*Klo + Qlo*Khi (log2 domain, scale folded) ----
        float s[8][4];
#pragma unroll
        for (int na = 0; na < 8; na++)
#pragma unroll
            for (int r2 = 0; r2 < 4; r2++) s[na][r2] = 0.f;

#pragma unroll
        for (int ks = 0; ks < 4; ks++) {
#pragma unroll
            for (int pr = 0; pr < 4; pr++) {
                uint32_t b4h[4], b4l[4];
                ldsm4(b4h, &Ks[pr * 16 + krow][ks * 16 + kcs]);
                ldsm4(b4l, &Ks[pr * 16 + krow][64 + ks * 16 + kcs]);
                mma16816(s[2 * pr],     qf[ks], b4h);
                mma16816(s[2 * pr + 1], qf[ks], b4h + 2);
                mma16816(s[2 * pr],     qf[ks], b4l);
                mma16816(s[2 * pr + 1], qf[ks], b4l + 2);
                mma16816(s[2 * pr],     qf[4 + ks], b4h);
                mma16816(s[2 * pr + 1], qf[4 + ks], b4h + 2);
            }
        }

        // ---- online softmax (log2 domain) ----
        float nm0 = mrow0, nm1 = mrow1;
#pragma unroll
        for (int na = 0; na < 8; na++) {
            nm0 = fmaxf(nm0, fmaxf(s[na][0], s[na][1]));
            nm1 = fmaxf(nm1, fmaxf(s[na][2], s[na][3]));
        }
        nm0 = fmaxf(nm0, __shfl_xor_sync(0xffffffffu, nm0, 1));
        nm0 = fmaxf(nm0, __shfl_xor_sync(0xffffffffu, nm0, 2));
        nm1 = fmaxf(nm1, __shfl_xor_sync(0xffffffffu, nm1, 1));
        nm1 = fmaxf(nm1, __shfl_xor_sync(0xffffffffu, nm1, 2));
        float corr0 = ex2(mrow0 - nm0), corr1 = ex2(mrow1 - nm1);
        mrow0 = nm0; mrow1 = nm1;
        lr0 *= corr0; lr1 *= corr1;
#pragma unroll
        for (int na = 0; na < 8; na++) {
            o[na][0] *= corr0; o[na][1] *= corr0;
            o[na][2] *= corr1; o[na][3] *= corr1;
        }

        // ---- P in registers, A-fragment layout ----
        uint32_t phA[8], phB[8], plA[8], plB[8];
#pragma unroll
        for (int na = 0; na < 8; na++) {
            float p0 = ex2(s[na][0] - nm0), p1 = ex2(s[na][1] - nm0);
            float p2 = ex2(s[na][2] - nm1), p3 = ex2(s[na][3] - nm1);
            lr0 += p0 + p1; lr1 += p2 + p3;
            phA[na] = pack_hi_lo(p0, p1, plA[na]);
            phB[na] = pack_hi_lo(p2, p3, plB[na]);
        }

        // ---- O += Phi*Vhi + Phi*Vlo + Plo*Vhi ----
#pragma unroll
        for (int ks = 0; ks < 4; ks++) {
            uint32_t afh[4] = { phA[2 * ks], phB[2 * ks], phA[2 * ks + 1], phB[2 * ks + 1] };
            uint32_t afl[4] = { plA[2 * ks], plB[2 * ks], plA[2 * ks + 1], plB[2 * ks + 1] };
#pragma unroll
            for (int pr = 0; pr < 4; pr++) {
                uint32_t b4h[4], b4l[4];
                ldsm4(b4h, &Vs[pr * 16 + krow][ks * 16 + kcs]);
                ldsm4(b4l, &Vs[pr * 16 + krow][64 + ks * 16 + kcs]);
                mma16816(o[2 * pr],     afh, b4h);
                mma16816(o[2 * pr + 1], afh, b4h + 2);
                mma16816(o[2 * pr],     afh, b4l);
                mma16816(o[2 * pr + 1], afh, b4l + 2);
                mma16816(o[2 * pr],     afl, b4h);
                mma16816(o[2 * pr + 1], afl, b4h + 2);
            }
        }
    }

    // ---- epilogue: normalize + write split y ----
    lr0 += __shfl_xor_sync(0xffffffffu, lr0, 1);
    lr0 += __shfl_xor_sync(0xffffffffu, lr0, 2);
    lr1 += __shfl_xor_sync(0xffffffffu, lr1, 1);
    lr1 += __shfl_xor_sync(0xffffffffu, lr1, 2);
    float inv0 = 1.f / lr0, inv1 = 1.f / lr1;

    int b = bh >> 4, h = bh & 15;
    int t0 = q0 + wid * 16 + g;
    size_t row0 = (size_t)(b * TT + t0) * 2048;
    size_t row1 = (size_t)(b * TT + t0 + 8) * 2048;
#pragma unroll
    for (int na = 0; na < 8; na++) {
        int c = h * 64 + na * 8 + 2 * q;
        uint32_t lo, hi;
        hi = pack_hi_lo(o[na][0] * inv0, o[na][1] * inv0, lo);
        *(uint32_t*)&g_ye[row0 + c] = hi;
        *(uint32_t*)&g_ye[row0 + 1024 + c] = lo;
        hi = pack_hi_lo(o[na][2] * inv1, o[na][3] * inv1, lo);
        *(uint32_t*)&g_ye[row1 + c] = hi;
        *(uint32_t*)&g_ye[row1 + 1024 + c] = lo;
    }
}

// ---------------- launch ----------------
extern "C" void kernel_launch(void* const* d_in, const int* in_sizes, int n_in,
                              void* d_out, int out_size)
{
    const float* x      = (const float*)d_in[0];
    const float* W_attn = (const float*)d_in[1];
    const float* W_proj = (const float*)d_in[2];
    float* out = (float*)d_out;

    cudaFuncSetAttribute(gemm_bf16x3<0, 3072>, cudaFuncAttributeMaxDynamicSharedMemorySize, 98304);
    cudaFuncSetAttribute(gemm_bf16x3<1, 1024>, cudaFuncAttributeMaxDynamicSharedMemorySize, 98304);
    cudaFuncSetAttribute(attn_kernel, cudaFuncAttributeMaxDynamicSharedMemorySize, 104448);

    conv_x_kernel<<<MB * 1024 / 256, 256>>>(x);
    conv_w_kernel<0><<<dim3(96, 32), 256>>>(W_attn, 3072);
    conv_w_kernel<1><<<dim3(32, 32), 256>>>(W_proj, 1024);
    gemm_bf16x3<0, 3072><<<dim3(24, 64), 256, 98304>>>(nullptr);
    rope_kernel<<<MB * 1024 / 256, 256>>>();
    vtrans_kernel<<<dim3(64, 64), 256>>>();
    attn_kernel<<<dim3(16, 64), 256, 104448>>>();
    gemm_bf16x3<1, 1024><<<dim3(8, 64), 256, 98304>>>(out);
}